// round 4
// baseline (speedup 1.0000x reference)
#include <cuda_runtime.h>

// Problem constants
#define B_TOT  2
#define E_TOT  2048
#define N1_TOT 96
#define K_TOT  32
#define CIN    64
#define CB     32
#define COUT   64
#define F_TOT  160          // 2*CIN + CB
#define WCNT   (F_TOT*COUT) // 10240
#define NEG_SLOPE 0.01f

#define EPC    28           // edges per CTA (4 groups x 7)
#define EPW    7            // edges per warp
#define NE_TOT (B_TOT*E_TOT)// 4096
#define GRID_M 147          // ceil(4096/28)

// Wbar = mean_g W_eq[g], PAIRED layout for LDS.128:
//   float index i = ip*128 + t*4 + slot -> Wbar[f=2*ip+(slot>>1)][o=2*t+(slot&1)]
__device__ float g_Wp[WCNT];

// ---------------------------------------------------------------------------
__global__ void prep_kernel(const float* __restrict__ W_eq, float* __restrict__ out) {
    int i = blockIdx.x * blockDim.x + threadIdx.x;
    if (i < WCNT) {
        const int ip = i >> 7, r = i & 127, t = r >> 2, slot = r & 3;
        const int f = 2 * ip + (slot >> 1);
        const int o = 2 * t + (slot & 1);
        const int idx = f * COUT + o;
        float s = W_eq[idx] + W_eq[WCNT + idx] + W_eq[2 * WCNT + idx] + W_eq[3 * WCNT + idx];
        g_Wp[i] = 0.25f * s;
    }
    if (i < B_TOT * K_TOT * COUT) out[i] = 0.0f;
}

// ---------------------------------------------------------------------------
// Uniform grid: 147 CTAs x 512 threads (16 warps), one CTA per SM.
// Warp w: f-quarter q=w>>2 (40 f's = 20 pair-iters), edge-group g=w&3 (7 edges).
// Thread t owns output pair {2t,2t+1}; fma.rn.f32x2; partials via smem psum.
// ---------------------------------------------------------------------------
__global__ void __launch_bounds__(512, 1) main_kernel(
    const float* __restrict__ sites1,
    const float* __restrict__ sites2,
    const float* __restrict__ bonds,
    const float* __restrict__ b_eq,
    const float* __restrict__ W_att,
    const float* __restrict__ b_att,
    const int*   __restrict__ idx1,
    const int*   __restrict__ idx2,
    float* __restrict__ out)
{
    extern __shared__ float smem[];
    float* Wsh = smem;                                        // 10240 f (40960 B)
    unsigned long long* vsh  =
        (unsigned long long*)(smem + WCNT);                   // 28 edges * 160 u64 (35840 B)
    unsigned long long* psum = vsh + EPC * F_TOT;             // 3 * 28 * 32 u64 (21504 B)

    const int tid  = threadIdx.x;
    const int lane = tid & 31;
    const int w    = tid >> 5;
    const int q    = w >> 2;      // f-quarter 0..3
    const int g    = w & 3;       // edge group 0..3

    // Stage Wbar (paired layout): 2560 float4 over 512 threads.
    {
        const float4* src = (const float4*)g_Wp;
        float4*       dst = (float4*)Wsh;
        #pragma unroll
        for (int i = 0; i < 5; i++) dst[i * 512 + tid] = src[i * 512 + tid];
    }

    // Gather: warp w stages edges le = 2w, 2w+1 (le<28). Dup into f32x2 halves.
    #pragma unroll
    for (int jj = 0; jj < 2; jj++) {
        const int le = 2 * w + jj;
        if (le < EPC) {
            int ei = blockIdx.x * EPC + le;
            if (ei > NE_TOT - 1) ei = NE_TOT - 1;   // clamp tail (masked at epilogue)
            const int b  = ei >> 11;
            const int e  = ei & (E_TOT - 1);
            const int i1 = idx1[e];
            const int i2 = idx2[e];
            #pragma unroll
            for (int m = 0; m < 5; m++) {
                const int f = lane + 32 * m;        // 0..159
                float v;
                if (f < CIN)            v = sites1[(b * N1_TOT + i1) * CIN + f];
                else if (f < 2 * CIN)   v = sites2[(b * K_TOT  + i2) * CIN + (f - CIN)];
                else                    v = bonds [(b * E_TOT  + e ) * CB  + (f - 2 * CIN)];
                const unsigned u = __float_as_uint(v);
                vsh[le * F_TOT + f] = ((unsigned long long)u << 32) | (unsigned long long)u;
            }
        }
    }
    __syncthreads();

    // Main loop: 20 pair-iters over this warp's f-quarter, 7 edges.
    const ulonglong2* Wq = (const ulonglong2*)Wsh;
    const unsigned long long* vb = vsh + (g * EPW) * F_TOT;

    unsigned long long acc[EPW];
    #pragma unroll
    for (int j = 0; j < EPW; j++) acc[j] = 0ull;

    const int ip0 = 20 * q;
    #pragma unroll 4
    for (int i = 0; i < 20; i++) {
        const int ip = ip0 + i;
        const ulonglong2 wq = Wq[ip * 32 + lane];
        ulonglong2 qv[EPW];
        #pragma unroll
        for (int j = 0; j < EPW; j++)
            qv[j] = ((const ulonglong2*)(vb + j * F_TOT))[ip];
        #pragma unroll
        for (int j = 0; j < EPW; j++) {
            asm("fma.rn.f32x2 %0, %1, %2, %0;" : "+l"(acc[j]) : "l"(qv[j].x), "l"(wq.x));
            asm("fma.rn.f32x2 %0, %1, %2, %0;" : "+l"(acc[j]) : "l"(qv[j].y), "l"(wq.y));
        }
    }

    // Publish partials for quarters 1..3.
    if (q != 0) {
        #pragma unroll
        for (int j = 0; j < EPW; j++) {
            const int le = g * EPW + j;
            psum[((q - 1) * EPC + le) * 32 + lane] = acc[j];
        }
    }
    __syncthreads();

    // Epilogue on q==0 warps (one warp per edge group).
    if (q == 0) {
        const float be0 = b_eq[2 * lane];
        const float be1 = b_eq[2 * lane + 1];
        const float wa0 = W_att[2 * lane];
        const float wa1 = W_att[2 * lane + 1];
        const float ba  = b_att[0];

        #pragma unroll
        for (int j = 0; j < EPW; j++) {
            const int le = g * EPW + j;
            float y0 = __uint_as_float((unsigned)(acc[j] & 0xffffffffull));
            float y1 = __uint_as_float((unsigned)(acc[j] >> 32));
            #pragma unroll
            for (int k = 0; k < 3; k++) {
                const unsigned long long pp = psum[(k * EPC + le) * 32 + lane];
                y0 += __uint_as_float((unsigned)(pp & 0xffffffffull));
                y1 += __uint_as_float((unsigned)(pp >> 32));
            }
            y0 += be0; y1 += be1;
            y0 = (y0 > 0.0f) ? y0 : NEG_SLOPE * y0;
            y1 = (y1 > 0.0f) ? y1 : NEG_SLOPE * y1;

            float p = y0 * wa0 + y1 * wa1;
            #pragma unroll
            for (int s = 16; s > 0; s >>= 1)
                p += __shfl_xor_sync(0xffffffffu, p, s);
            const float att = 1.0f / (1.0f + __expf(-(p + ba)));

            const int ei = blockIdx.x * EPC + le;
            if (ei < NE_TOT) {
                const int b  = ei >> 11;
                const int e  = ei & (E_TOT - 1);
                const int k2 = idx2[e];
                float* dst = out + ((size_t)(b * K_TOT + k2)) * COUT + 2 * lane;
                atomicAdd(dst,     y0 * att);
                atomicAdd(dst + 1, y1 * att);
            }
        }
    }
}

// ---------------------------------------------------------------------------
extern "C" void kernel_launch(void* const* d_in, const int* in_sizes, int n_in,
                              void* d_out, int out_size)
{
    const float* sites1 = (const float*)d_in[0];
    const float* sites2 = (const float*)d_in[1];
    const float* bonds  = (const float*)d_in[2];
    const float* W_eq   = (const float*)d_in[3];
    const float* b_eq   = (const float*)d_in[4];
    const float* W_att  = (const float*)d_in[5];
    const float* b_att  = (const float*)d_in[6];
    // d_in[7] = idx2_oh (unused — collapsed analytically)
    const int*   idx1   = (const int*)d_in[8];
    const int*   idx2   = (const int*)d_in[9];
    // d_in[10], d_in[11] = perms1/perms2 (unused — permutations cancel)
    float* out = (float*)d_out;

    const int smem_bytes = WCNT * 4                 // Wsh  (40960)
                         + EPC * F_TOT * 8          // vsh  (35840)
                         + 3 * EPC * 32 * 8;        // psum (21504)
    cudaFuncSetAttribute(main_kernel,
                         cudaFuncAttributeMaxDynamicSharedMemorySize, smem_bytes);

    prep_kernel<<<40, 256>>>(W_eq, out);

    // Uniform grid: 147 CTAs x 512 threads, 28 edges each (tail masked).
    main_kernel<<<GRID_M, 512, smem_bytes>>>(sites1, sites2, bonds,
                                             b_eq, W_att, b_att,
                                             idx1, idx2, out);
}